// round 1
// baseline (speedup 1.0000x reference)
#include <cuda_runtime.h>
#include <math.h>

#define BATCH 1024
#define NTOK  64
#define CDIM  256
#define HEADS 8
#define HDIM  32
#define NWIN  64
#define QKVN  768

// ---------------- scratch (device globals; no allocations) ----------------
__device__ float g_qkv[BATCH * NTOK * QKVN];   // (b*64+t, 768) row-major
__device__ float g_ctx[BATCH * NTOK * CDIM];   // (b*64+t, 256) row-major
__device__ float g_rpb[HEADS * NTOK * NTOK];   // (h, p, q)

// ---------------- relative position bias (MLP + gather + sigmoid) ----------
__global__ __launch_bounds__(256) void rpb_kernel(
    const float* __restrict__ w1, const float* __restrict__ b1,
    const float* __restrict__ w2)
{
    __shared__ float hbt[225][8];
    int tid = threadIdx.x;
    if (tid < 225) {
        int i = tid / 15, j = tid % 15;
        float ri = (float)(i - 7) * (8.0f / 7.0f);
        float rj = (float)(j - 7) * (8.0f / 7.0f);
        // sign(t) * log2(|t|+1) / log2(8)
        float t0 = copysignf(log2f(fabsf(ri) + 1.0f) * (1.0f / 3.0f), ri);
        float t1 = copysignf(log2f(fabsf(rj) + 1.0f) * (1.0f / 3.0f), rj);
        if (ri == 0.0f) t0 = 0.0f;
        if (rj == 0.0f) t1 = 0.0f;
        float acc[8];
        #pragma unroll
        for (int h = 0; h < 8; h++) acc[h] = 0.0f;
        for (int u = 0; u < 512; u++) {
            float hv = fmaxf(t0 * w1[2 * u] + t1 * w1[2 * u + 1] + b1[u], 0.0f);
            #pragma unroll
            for (int h = 0; h < 8; h++) acc[h] += hv * w2[h * 512 + u];
        }
        #pragma unroll
        for (int h = 0; h < 8; h++) hbt[tid][h] = acc[h];
    }
    __syncthreads();
    for (int idx = tid; idx < HEADS * NTOK * NTOK; idx += 256) {
        int h = idx >> 12;
        int p = (idx >> 6) & 63;
        int q = idx & 63;
        int dy = (p >> 3) - (q >> 3) + 7;
        int dx = (p & 7) - (q & 7) + 7;
        float v = hbt[dy * 15 + dx][h];
        g_rpb[idx] = 16.0f / (1.0f + expf(-v));
    }
}

// ---------------- tiled SGEMM: C[M,N] = A[M,K] * B[N,K]^T + bias ------------
#define BM 128
#define BN 128
#define BK 16

__device__ __forceinline__ float get_bias(int n, const float* b0,
                                          const float* b1, int mode)
{
    if (mode) return b0[n];
    if (n < 256) return b0[n];
    if (n < 512) return 0.0f;
    return b1[n - 512];
}

__device__ __forceinline__ void sgemm_body(
    const float* __restrict__ A, const float* __restrict__ B,
    float* __restrict__ C, int K, int N,
    const float* __restrict__ bias0, const float* __restrict__ bias1, int mode)
{
    __shared__ float As[BK][BM];
    __shared__ float Bs[BK][BN];
    int tid = threadIdx.x;
    int mBase = blockIdx.y * BM;
    int nBase = blockIdx.x * BN;
    int ty = tid >> 4, tx = tid & 15;

    float acc[8][8];
    #pragma unroll
    for (int i = 0; i < 8; i++)
        #pragma unroll
        for (int j = 0; j < 8; j++) acc[i][j] = 0.0f;

    for (int kt = 0; kt < K; kt += BK) {
        #pragma unroll
        for (int r = 0; r < 2; r++) {
            int idx = tid + r * 256;
            int row = idx >> 2;
            int k4 = (idx & 3) << 2;
            float4 va = *(const float4*)&A[(size_t)(mBase + row) * K + kt + k4];
            As[k4 + 0][row] = va.x; As[k4 + 1][row] = va.y;
            As[k4 + 2][row] = va.z; As[k4 + 3][row] = va.w;
            float4 vb = *(const float4*)&B[(size_t)(nBase + row) * K + kt + k4];
            Bs[k4 + 0][row] = vb.x; Bs[k4 + 1][row] = vb.y;
            Bs[k4 + 2][row] = vb.z; Bs[k4 + 3][row] = vb.w;
        }
        __syncthreads();
        #pragma unroll
        for (int kk = 0; kk < BK; kk++) {
            float a[8], b[8];
            *(float4*)&a[0] = *(const float4*)&As[kk][ty * 8];
            *(float4*)&a[4] = *(const float4*)&As[kk][ty * 8 + 4];
            *(float4*)&b[0] = *(const float4*)&Bs[kk][tx * 8];
            *(float4*)&b[4] = *(const float4*)&Bs[kk][tx * 8 + 4];
            #pragma unroll
            for (int i = 0; i < 8; i++)
                #pragma unroll
                for (int j = 0; j < 8; j++)
                    acc[i][j] += a[i] * b[j];
        }
        __syncthreads();
    }

    #pragma unroll
    for (int i = 0; i < 8; i++) {
        int m = mBase + ty * 8 + i;
        #pragma unroll
        for (int jj = 0; jj < 8; jj += 4) {
            int n = nBase + tx * 8 + jj;
            float4 v;
            v.x = acc[i][jj + 0] + get_bias(n + 0, bias0, bias1, mode);
            v.y = acc[i][jj + 1] + get_bias(n + 1, bias0, bias1, mode);
            v.z = acc[i][jj + 2] + get_bias(n + 2, bias0, bias1, mode);
            v.w = acc[i][jj + 3] + get_bias(n + 3, bias0, bias1, mode);
            *(float4*)&C[(size_t)m * N + n] = v;
        }
    }
}

__global__ __launch_bounds__(256) void qkv_gemm_kernel(
    const float* __restrict__ x, const float* __restrict__ w,
    const float* __restrict__ qb, const float* __restrict__ vb)
{
    sgemm_body(x, w, g_qkv, CDIM, QKVN, qb, vb, 0);
}

__global__ __launch_bounds__(256) void proj_gemm_kernel(
    const float* __restrict__ w, float* __restrict__ out,
    const float* __restrict__ pb)
{
    sgemm_body(g_ctx, w, out, CDIM, CDIM, pb, nullptr, 1);
}

// ---------------- per-(window,head) attention ------------------------------
__global__ __launch_bounds__(256) void attn_kernel(
    const float* __restrict__ mask, const float* __restrict__ logit_scale)
{
    __shared__ float qs[HDIM][68];     // transposed [d][t], pad for banks
    __shared__ float ks[HDIM][68];
    __shared__ float vs[NTOK][HDIM];   // [t][d]
    __shared__ float sm[NTOK][65];     // scores, pad 65

    int b = blockIdx.x >> 3;
    int h = blockIdx.x & 7;
    int tid = threadIdx.x;

    // load q,k transposed, v normal (global access fully coalesced per 128B)
    #pragma unroll
    for (int r = 0; r < 8; r++) {
        int idx = tid + r * 256;              // 2048 = 64*32
        int t = idx >> 5, d = idx & 31;
        size_t base = (size_t)(b * NTOK + t) * QKVN + h * HDIM + d;
        float qv = g_qkv[base];
        float kv = g_qkv[base + CDIM];
        float vv = g_qkv[base + 2 * CDIM];
        qs[d][t] = qv;
        ks[d][t] = kv;
        vs[t][d] = vv;
    }
    __syncthreads();

    // normalize q,k rows (columns of transposed layout)
    if (tid < 128) {
        int t = tid & 63;
        float (*arr)[68] = (tid < 64) ? qs : ks;
        float ss = 0.0f;
        #pragma unroll
        for (int d = 0; d < HDIM; d++) { float v = arr[d][t]; ss += v * v; }
        float inv = 1.0f / fmaxf(sqrtf(ss), 1e-12f);
        #pragma unroll
        for (int d = 0; d < HDIM; d++) arr[d][t] *= inv;
    }
    __syncthreads();

    float scale = expf(fminf(logit_scale[h], 4.605170185988091f)); // ln(100)
    int wmask = b & (NWIN - 1);

    // S = qn @ kn^T : 4x4 fragments, 16x16 thread grid
    {
        int trow = tid >> 4, tcol = tid & 15;
        float s4[4][4];
        #pragma unroll
        for (int i = 0; i < 4; i++)
            #pragma unroll
            for (int j = 0; j < 4; j++) s4[i][j] = 0.0f;
        #pragma unroll
        for (int d = 0; d < HDIM; d++) {
            float4 a = *(const float4*)&qs[d][trow * 4];
            float4 bb = *(const float4*)&ks[d][tcol * 4];
            float av[4] = {a.x, a.y, a.z, a.w};
            float bv[4] = {bb.x, bb.y, bb.z, bb.w};
            #pragma unroll
            for (int i = 0; i < 4; i++)
                #pragma unroll
                for (int j = 0; j < 4; j++) s4[i][j] += av[i] * bv[j];
        }
        #pragma unroll
        for (int i = 0; i < 4; i++) {
            int p = trow * 4 + i;
            float4 rv = *(const float4*)&g_rpb[(h * NTOK + p) * NTOK + tcol * 4];
            float4 mv = *(const float4*)&mask[((size_t)wmask * NTOK + p) * NTOK + tcol * 4];
            sm[p][tcol * 4 + 0] = s4[i][0] * scale + rv.x + mv.x;
            sm[p][tcol * 4 + 1] = s4[i][1] * scale + rv.y + mv.y;
            sm[p][tcol * 4 + 2] = s4[i][2] * scale + rv.z + mv.z;
            sm[p][tcol * 4 + 3] = s4[i][3] * scale + rv.w + mv.w;
        }
    }
    __syncthreads();

    // softmax per row (64 rows, one thread each; padded smem -> conflict-free)
    if (tid < 64) {
        float mx = -1e30f;
        #pragma unroll 8
        for (int c = 0; c < NTOK; c++) mx = fmaxf(mx, sm[tid][c]);
        float sum = 0.0f;
        #pragma unroll 8
        for (int c = 0; c < NTOK; c++) {
            float e = expf(sm[tid][c] - mx);
            sm[tid][c] = e;
            sum += e;
        }
        float inv = 1.0f / sum;
        #pragma unroll 8
        for (int c = 0; c < NTOK; c++) sm[tid][c] *= inv;
    }
    __syncthreads();

    // O = S @ V : 4x4 fragments, 128 threads (16 x 8 tiles)
    if (tid < 128) {
        int prow = tid >> 3, pcol = tid & 7;
        float o[4][4];
        #pragma unroll
        for (int i = 0; i < 4; i++)
            #pragma unroll
            for (int j = 0; j < 4; j++) o[i][j] = 0.0f;
        #pragma unroll 4
        for (int m = 0; m < NTOK; m++) {
            float sv[4];
            #pragma unroll
            for (int i = 0; i < 4; i++) sv[i] = sm[prow * 4 + i][m];
            float4 vv = *(const float4*)&vs[m][pcol * 4];
            float bv[4] = {vv.x, vv.y, vv.z, vv.w};
            #pragma unroll
            for (int i = 0; i < 4; i++)
                #pragma unroll
                for (int j = 0; j < 4; j++) o[i][j] += sv[i] * bv[j];
        }
        #pragma unroll
        for (int i = 0; i < 4; i++) {
            int p = prow * 4 + i;
            float4 v = make_float4(o[i][0], o[i][1], o[i][2], o[i][3]);
            *(float4*)&g_ctx[(size_t)(b * NTOK + p) * CDIM + h * HDIM + pcol * 4] = v;
        }
    }
}

// ---------------- entry ----------------------------------------------------
extern "C" void kernel_launch(void* const* d_in, const int* in_sizes, int n_in,
                              void* d_out, int out_size)
{
    (void)in_sizes; (void)n_in; (void)out_size;
    const float* x           = (const float*)d_in[0];
    const float* mask        = (const float*)d_in[1];
    const float* qkv_w       = (const float*)d_in[2];
    const float* q_bias      = (const float*)d_in[3];
    const float* v_bias      = (const float*)d_in[4];
    const float* logit_scale = (const float*)d_in[5];
    const float* mlp_w1      = (const float*)d_in[6];
    const float* mlp_b1      = (const float*)d_in[7];
    const float* mlp_w2      = (const float*)d_in[8];
    const float* proj_w      = (const float*)d_in[9];
    const float* proj_b      = (const float*)d_in[10];
    float* out = (float*)d_out;

    rpb_kernel<<<1, 256>>>(mlp_w1, mlp_b1, mlp_w2);

    dim3 g_qkv_grid(QKVN / BN, (BATCH * NTOK) / BM);   // (6, 512)
    qkv_gemm_kernel<<<g_qkv_grid, 256>>>(x, qkv_w, q_bias, v_bias);

    attn_kernel<<<BATCH * HEADS, 256>>>(mask, logit_scale);

    dim3 g_proj_grid(CDIM / BN, (BATCH * NTOK) / BM);  // (2, 512)
    proj_gemm_kernel<<<g_proj_grid, 256>>>(proj_w, out, proj_b);
}